// round 2
// baseline (speedup 1.0000x reference)
#include <cuda_runtime.h>
#include <math.h>

#define BSZ 2
#define HH 64
#define WW 80
#define NQ (HH*WW)          // 5120
#define EE 576
#define HEADS 18
#define HD 32
#define NPTS 12
#define NFR 3
#define DDEP 5              // 2*NF-1
#define NV (NQ*DDEP)        // 25600

// ---------------- scratch (device globals; no allocation allowed) ----------
__device__ float g_q   [(size_t)BSZ*NQ*EE];              // 23.6 MB
__device__ float g_v   [(size_t)BSZ*NV*EE];              // 118 MB
__device__ float g_offs[(size_t)BSZ*NQ*HEADS*NPTS*3];    // 26.5 MB
__device__ float g_attn[(size_t)BSZ*NQ*HEADS*NPTS];      // 8.8 MB
__device__ float g_samp[(size_t)BSZ*NQ*EE];              // 23.6 MB

// ---------------- q = query + query_pos ------------------------------------
__global__ void add_kernel(const float* __restrict__ a, const float* __restrict__ b,
                           float* __restrict__ c, int n4) {
    int i = blockIdx.x * blockDim.x + threadIdx.x;
    if (i < n4) {
        float4 x = reinterpret_cast<const float4*>(a)[i];
        float4 y = reinterpret_cast<const float4*>(b)[i];
        float4 z;
        z.x = x.x + y.x; z.y = x.y + y.y; z.z = x.z + y.z; z.w = x.w + y.w;
        reinterpret_cast<float4*>(c)[i] = z;
    }
}

// ---------------- fp32 SGEMM: C[M,N] = A[M,K] @ B[K,N] + bias[N] -----------
// BM=128, BN=64, BK=16, 256 threads, 8x4 per-thread tile.
// Requires: K % 16 == 0, K % 4 == 0, N % 4 == 0, M % 128 == 0 (all true here).
__global__ __launch_bounds__(256)
void sgemm_bias(const float* __restrict__ A, const float* __restrict__ B,
                const float* __restrict__ bias, float* __restrict__ C,
                int M, int N, int K) {
    const int BM = 128, BN = 64, BK = 16;
    __shared__ float As[BK][BM];
    __shared__ float Bs[BK][BN];

    int tid = threadIdx.x;
    int bm = blockIdx.y * BM;
    int bn = blockIdx.x * BN;
    int tx = tid & 15;           // 0..15 -> col group (x4)
    int ty = tid >> 4;           // 0..15 -> row group (x8)

    float acc[8][4];
#pragma unroll
    for (int i = 0; i < 8; i++)
#pragma unroll
        for (int j = 0; j < 4; j++) acc[i][j] = 0.f;

    for (int k0 = 0; k0 < K; k0 += BK) {
        // A tile: 128x16 = 512 float4, 2 per thread
#pragma unroll
        for (int t = 0; t < 2; t++) {
            int idx = tid + t * 256;             // 0..511
            int r = idx >> 2;                    // 0..127
            int c = (idx & 3) << 2;              // 0,4,8,12
            float4 av = *reinterpret_cast<const float4*>(
                &A[(size_t)(bm + r) * K + k0 + c]);
            As[c + 0][r] = av.x;
            As[c + 1][r] = av.y;
            As[c + 2][r] = av.z;
            As[c + 3][r] = av.w;
        }
        // B tile: 16x64 = 256 float4, 1 per thread
        {
            int r = tid >> 4;                    // 0..15
            int c = (tid & 15) << 2;             // 0..60
            int col = bn + c;
            float4 bv;
            if (col + 3 < N) {
                bv = *reinterpret_cast<const float4*>(&B[(size_t)(k0 + r) * N + col]);
            } else {
                bv.x = (col + 0 < N) ? B[(size_t)(k0 + r) * N + col + 0] : 0.f;
                bv.y = (col + 1 < N) ? B[(size_t)(k0 + r) * N + col + 1] : 0.f;
                bv.z = (col + 2 < N) ? B[(size_t)(k0 + r) * N + col + 2] : 0.f;
                bv.w = (col + 3 < N) ? B[(size_t)(k0 + r) * N + col + 3] : 0.f;
            }
            *reinterpret_cast<float4*>(&Bs[r][c]) = bv;
        }
        __syncthreads();

#pragma unroll
        for (int kk = 0; kk < BK; kk++) {
            float ar[8], br[4];
#pragma unroll
            for (int i = 0; i < 8; i++) ar[i] = As[kk][ty * 8 + i];
#pragma unroll
            for (int j = 0; j < 4; j++) br[j] = Bs[kk][tx * 4 + j];
#pragma unroll
            for (int i = 0; i < 8; i++)
#pragma unroll
                for (int j = 0; j < 4; j++) acc[i][j] += ar[i] * br[j];
        }
        __syncthreads();
    }

#pragma unroll
    for (int i = 0; i < 8; i++) {
        int r = bm + ty * 8 + i;
        if (r >= M) continue;
#pragma unroll
        for (int j = 0; j < 4; j++) {
            int c = bn + tx * 4 + j;
            if (c < N) C[(size_t)r * N + c] = acc[i][j] + bias[c];
        }
    }
}

// ---------------- deformable 3D trilinear sampling -------------------------
// One warp per (b, head, q); lane = element of head-dim (HD == 32).
__global__ __launch_bounds__(256)
void deform_sample(const float* __restrict__ v, const float* __restrict__ offs,
                   const float* __restrict__ lg, float* __restrict__ out) {
    int wg = (blockIdx.x * blockDim.x + threadIdx.x) >> 5;
    int lane = threadIdx.x & 31;
    const int total = BSZ * HEADS * NQ;
    if (wg >= total) return;

    int q    = wg % NQ;
    int head = (wg / NQ) % HEADS;
    int b    = wg / (NQ * HEADS);

    int qx = q % WW;
    int qy = q / WW;
    float refx = ((float)qx + 0.5f) / (float)WW;
    float refy = ((float)qy + 0.5f) / (float)HH;

    // softmax over the 12 point logits (broadcast per-lane, cheap)
    const float* lgp = lg + (((size_t)b * NQ + q) * HEADS + head) * NPTS;
    float wt[NPTS];
    float mx = -1e30f;
#pragma unroll
    for (int p = 0; p < NPTS; p++) mx = fmaxf(mx, lgp[p]);
    float s = 0.f;
#pragma unroll
    for (int p = 0; p < NPTS; p++) { wt[p] = expf(lgp[p] - mx); s += wt[p]; }
    float invs = 1.f / s;

    const float* offp = offs + ((((size_t)b * NQ + q) * HEADS + head) * NPTS) * 3;
    const float* vbh = v + (size_t)b * NV * EE + head * HD + lane;

    float acc = 0.f;
#pragma unroll
    for (int p = 0; p < NPTS; p++) {
        float ox = offp[p * 3 + 0];
        float oy = offp[p * 3 + 1];
        float oz = offp[p * 3 + 2];
        // exact reference arithmetic: loc = ref + off/norm ; pix = loc*size - 0.5
        float x = (refx + ox / (float)WW) * (float)WW - 0.5f;
        float y = (refy + oy / (float)HH) * (float)HH - 0.5f;
        float z = (oz / (float)NFR) * (float)DDEP - 0.5f;
        float x0f = floorf(x), y0f = floorf(y), z0f = floorf(z);
        float fx = x - x0f, fy = y - y0f, fz = z - z0f;
        int ix0 = (int)x0f, iy0 = (int)y0f, iz0 = (int)z0f;
        float ap = wt[p] * invs;
#pragma unroll
        for (int dz = 0; dz < 2; dz++) {
            int zi = iz0 + dz;
            if ((unsigned)zi >= DDEP) continue;
            float wz = dz ? fz : (1.f - fz);
#pragma unroll
            for (int dy = 0; dy < 2; dy++) {
                int yi = iy0 + dy;
                if ((unsigned)yi >= HH) continue;
                float wzy = wz * (dy ? fy : (1.f - fy));
#pragma unroll
                for (int dx = 0; dx < 2; dx++) {
                    int xi = ix0 + dx;
                    if ((unsigned)xi >= WW) continue;
                    float wgt = wzy * (dx ? fx : (1.f - fx));
                    int idx = (zi * HH + yi) * WW + xi;
                    acc += ap * wgt * __ldg(&vbh[(size_t)idx * EE]);
                }
            }
        }
    }
    out[((size_t)b * NQ + q) * EE + head * HD + lane] = acc;
}

// ---------------- launch ---------------------------------------------------
extern "C" void kernel_launch(void* const* d_in, const int* in_sizes, int n_in,
                              void* d_out, int out_size) {
    const float* query  = (const float*)d_in[0];
    const float* value  = (const float*)d_in[1];
    const float* qpos   = (const float*)d_in[2];
    const float* W_off  = (const float*)d_in[3];
    const float* b_off  = (const float*)d_in[4];
    const float* W_attn = (const float*)d_in[5];
    const float* b_attn = (const float*)d_in[6];
    const float* W_v    = (const float*)d_in[7];
    const float* b_v    = (const float*)d_in[8];
    const float* W_out  = (const float*)d_in[9];
    const float* b_out  = (const float*)d_in[10];
    float* out = (float*)d_out;

    float *q_s, *v_s, *offs_s, *attn_s, *samp_s;
    cudaGetSymbolAddress((void**)&q_s,    g_q);
    cudaGetSymbolAddress((void**)&v_s,    g_v);
    cudaGetSymbolAddress((void**)&offs_s, g_offs);
    cudaGetSymbolAddress((void**)&attn_s, g_attn);
    cudaGetSymbolAddress((void**)&samp_s, g_samp);

    // 1) q = query + query_pos
    {
        int n4 = (BSZ * NQ * EE) / 4;
        add_kernel<<<(n4 + 255) / 256, 256>>>(query, qpos, q_s, n4);
    }
    // 2) v = value @ W_v + b_v     (M=51200, N=576, K=576)
    {
        dim3 grid(EE / 64, (BSZ * NV) / 128);
        sgemm_bias<<<grid, 256>>>(value, W_v, b_v, v_s, BSZ * NV, EE, EE);
    }
    // 3) offs = q @ W_off + b_off  (M=10240, N=648, K=576)
    {
        int N = HEADS * NPTS * 3;
        dim3 grid((N + 63) / 64, (BSZ * NQ) / 128);
        sgemm_bias<<<grid, 256>>>(q_s, W_off, b_off, offs_s, BSZ * NQ, N, EE);
    }
    // 4) attn logits = q @ W_attn + b_attn  (M=10240, N=216, K=576)
    {
        int N = HEADS * NPTS;
        dim3 grid((N + 63) / 64, (BSZ * NQ) / 128);
        sgemm_bias<<<grid, 256>>>(q_s, W_attn, b_attn, attn_s, BSZ * NQ, N, EE);
    }
    // 5) trilinear sampling + softmax weighting
    {
        int warps = BSZ * HEADS * NQ;               // 184320
        int blocks = (warps + 7) / 8;               // 8 warps/block
        deform_sample<<<blocks, 256>>>(v_s, offs_s, attn_s, samp_s);
    }
    // 6) out = samp @ W_out + b_out  (M=10240, N=576, K=576)
    {
        dim3 grid(EE / 64, (BSZ * NQ) / 128);
        sgemm_bias<<<grid, 256>>>(samp_s, W_out, b_out, out, BSZ * NQ, EE, EE);
    }
}

// round 4
// speedup vs baseline: 1.5899x; 1.5899x over previous
#include <cuda_runtime.h>
#include <cuda_bf16.h>
#include <cstdint>
#include <math.h>

#define BSZ 2
#define HH 64
#define WW 80
#define NQ (HH*WW)          // 5120
#define EE 576
#define HEADS 18
#define HD 32
#define NPTS 12
#define NFR 3
#define DDEP 5
#define NV (NQ*DDEP)        // 25600

// ---------------- scratch (device globals; no allocation allowed) ----------
__device__ float g_q   [(size_t)BSZ*NQ*EE];
__device__ float g_v   [(size_t)BSZ*NV*EE];
__device__ float g_offs[(size_t)BSZ*NQ*HEADS*NPTS*3];
__device__ float g_attn[(size_t)BSZ*NQ*HEADS*NPTS];
__device__ float g_samp[(size_t)BSZ*NQ*EE];

// ================= helpers =================================================
__device__ __forceinline__ uint32_t smem_u32(const void* p) {
    uint32_t a;
    asm("{ .reg .u64 t; cvta.to.shared.u64 t, %1; cvt.u32.u64 %0, t; }" : "=r"(a) : "l"(p));
    return a;
}
__device__ __forceinline__ void ldsm_x4(uint32_t* r, uint32_t addr) {
    asm volatile("ldmatrix.sync.aligned.m8n8.x4.shared.b16 {%0,%1,%2,%3}, [%4];"
                 : "=r"(r[0]), "=r"(r[1]), "=r"(r[2]), "=r"(r[3]) : "r"(addr));
}
__device__ __forceinline__ void ldsm_x4_t(uint32_t* r, uint32_t addr) {
    asm volatile("ldmatrix.sync.aligned.m8n8.x4.trans.shared.b16 {%0,%1,%2,%3}, [%4];"
                 : "=r"(r[0]), "=r"(r[1]), "=r"(r[2]), "=r"(r[3]) : "r"(addr));
}
__device__ __forceinline__ void mma_bf16(float* c, const uint32_t* a, const uint32_t* b) {
    asm volatile(
        "mma.sync.aligned.m16n8k16.row.col.f32.bf16.bf16.f32 "
        "{%0,%1,%2,%3}, {%4,%5,%6,%7}, {%8,%9}, {%0,%1,%2,%3};"
        : "+f"(c[0]), "+f"(c[1]), "+f"(c[2]), "+f"(c[3])
        : "r"(a[0]), "r"(a[1]), "r"(a[2]), "r"(a[3]), "r"(b[0]), "r"(b[1]));
}
__device__ __forceinline__ void splitf(float f, unsigned short& h, unsigned short& l) {
    __nv_bfloat16 bh = __float2bfloat16(f);
    float r = f - __bfloat162float(bh);
    __nv_bfloat16 bl = __float2bfloat16(r);
    h = reinterpret_cast<unsigned short&>(bh);
    l = reinterpret_cast<unsigned short&>(bl);
}
__device__ __forceinline__ void split4(float4 v, uint2& hi, uint2& lo) {
    unsigned short h0, h1, h2, h3, l0, l1, l2, l3;
    splitf(v.x, h0, l0); splitf(v.y, h1, l1);
    splitf(v.z, h2, l2); splitf(v.w, h3, l3);
    hi.x = (uint32_t)h0 | ((uint32_t)h1 << 16);
    hi.y = (uint32_t)h2 | ((uint32_t)h3 << 16);
    lo.x = (uint32_t)l0 | ((uint32_t)l1 << 16);
    lo.y = (uint32_t)l2 | ((uint32_t)l3 << 16);
}

// ================= HMMA GEMM (split-bf16) ==================================
// C[M,N] = A[M,K] @ B[K,N] + bias[N]   (B used directly, [K][N] row-major)
// Block: 128x96x32, 256 threads, 8 warps (4m x 2n), warp tile 32x48.
#define BM 128
#define BN 96
#define BK 32
#define SA 80            // A smem row stride bytes (64 data + pad), mult of 16
#define SB 208           // B smem row stride bytes (192 data + pad), mult of 16
#define ASZ (128*SA)     // 10240
#define BTSZ (32*SB)     // 6656
#define OFF_AH 0
#define OFF_AL ASZ
#define OFF_BH (2*ASZ)
#define OFF_BL (2*ASZ + BTSZ)
#define BUF_SZ (2*ASZ + 2*BTSZ)   // 33792
#define SMEM_TOT (2*BUF_SZ)       // 67584

__global__ __launch_bounds__(256, 1)
void gemm_mma(const float* __restrict__ A, const float* __restrict__ B,
              const float* __restrict__ bias, float* __restrict__ C,
              int M, int N, int K) {
    extern __shared__ char smem[];
    uint32_t sbase = smem_u32(smem);
    const int tid = threadIdx.x;
    const int lane = tid & 31, wid = tid >> 5;
    const int warp_m = wid & 3, warp_n = wid >> 2;
    const int bm = blockIdx.y * BM;
    const int bn = blockIdx.x * BN;
    const int nchunk = K / BK;    // 18

    float acc[2][6][4];
#pragma unroll
    for (int mi = 0; mi < 2; mi++)
#pragma unroll
        for (int ni = 0; ni < 6; ni++)
#pragma unroll
            for (int j = 0; j < 4; j++) acc[mi][ni][j] = 0.f;

    float4 areg[4], breg[3];

    // ---- prefetch chunk 0 into registers ----
    {
        const int k0 = 0;
#pragma unroll
        for (int t = 0; t < 4; t++) {
            int idx = tid + t * 256, r = idx >> 3, c4 = idx & 7;
            areg[t] = *reinterpret_cast<const float4*>(&A[(size_t)(bm + r) * K + k0 + c4 * 4]);
        }
#pragma unroll
        for (int t = 0; t < 3; t++) {
            int idx = tid + t * 256, r = idx / 24, c4 = idx % 24;
            int col = bn + c4 * 4;
            float4 v = make_float4(0.f, 0.f, 0.f, 0.f);
            if (col < N) v = *reinterpret_cast<const float4*>(&B[(size_t)(k0 + r) * N + col]);
            breg[t] = v;
        }
    }

    int buf = 0;
    for (int c = 0; c < nchunk; c++) {
        // ---- convert + store to smem[buf] ----
        char* sb = smem + buf * BUF_SZ;
#pragma unroll
        for (int t = 0; t < 4; t++) {
            int idx = tid + t * 256, r = idx >> 3, c4 = idx & 7;
            uint2 hi, lo; split4(areg[t], hi, lo);
            uint32_t o = r * SA + c4 * 8;
            *reinterpret_cast<uint2*>(sb + OFF_AH + o) = hi;
            *reinterpret_cast<uint2*>(sb + OFF_AL + o) = lo;
        }
#pragma unroll
        for (int t = 0; t < 3; t++) {
            int idx = tid + t * 256, r = idx / 24, c4 = idx % 24;
            uint2 hi, lo; split4(breg[t], hi, lo);
            uint32_t o = r * SB + c4 * 8;
            *reinterpret_cast<uint2*>(sb + OFF_BH + o) = hi;
            *reinterpret_cast<uint2*>(sb + OFF_BL + o) = lo;
        }
        __syncthreads();

        // ---- prefetch next chunk ----
        if (c + 1 < nchunk) {
            const int k0 = (c + 1) * BK;
#pragma unroll
            for (int t = 0; t < 4; t++) {
                int idx = tid + t * 256, r = idx >> 3, c4 = idx & 7;
                areg[t] = *reinterpret_cast<const float4*>(&A[(size_t)(bm + r) * K + k0 + c4 * 4]);
            }
#pragma unroll
            for (int t = 0; t < 3; t++) {
                int idx = tid + t * 256, r = idx / 24, c4 = idx % 24;
                int col = bn + c4 * 4;
                float4 v = make_float4(0.f, 0.f, 0.f, 0.f);
                if (col < N) v = *reinterpret_cast<const float4*>(&B[(size_t)(k0 + r) * N + col]);
                breg[t] = v;
            }
        }

        // ---- compute on smem[buf] ----
        uint32_t sbuf = sbase + buf * BUF_SZ;
#pragma unroll
        for (int ks = 0; ks < 2; ks++) {
            uint32_t a_hi[2][4], a_lo[2][4], b_hi[6][2], b_lo[6][2];
#pragma unroll
            for (int mi = 0; mi < 2; mi++) {
                uint32_t ad = sbuf + OFF_AH
                    + (warp_m * 32 + mi * 16 + (lane & 15)) * SA
                    + ks * 32 + (lane >> 4) * 16;
                ldsm_x4(a_hi[mi], ad);
                ldsm_x4(a_lo[mi], ad + ASZ);
            }
#pragma unroll
            for (int nt = 0; nt < 3; nt++) {
                uint32_t bd = sbuf + OFF_BH
                    + (ks * 16 + (lane & 15)) * SB
                    + (warp_n * 48 + nt * 16) * 2 + (lane >> 4) * 16;
                uint32_t r[4];
                ldsm_x4_t(r, bd);
                b_hi[nt * 2][0] = r[0]; b_hi[nt * 2][1] = r[1];
                b_hi[nt * 2 + 1][0] = r[2]; b_hi[nt * 2 + 1][1] = r[3];
                ldsm_x4_t(r, bd + BTSZ);
                b_lo[nt * 2][0] = r[0]; b_lo[nt * 2][1] = r[1];
                b_lo[nt * 2 + 1][0] = r[2]; b_lo[nt * 2 + 1][1] = r[3];
            }
#pragma unroll
            for (int mi = 0; mi < 2; mi++)
#pragma unroll
                for (int ni = 0; ni < 6; ni++) {
                    mma_bf16(acc[mi][ni], a_hi[mi], b_hi[ni]);
                    mma_bf16(acc[mi][ni], a_hi[mi], b_lo[ni]);
                    mma_bf16(acc[mi][ni], a_lo[mi], b_hi[ni]);
                }
        }
        __syncthreads();
        buf ^= 1;
    }

    // ---- epilogue: registers -> global + bias ----
    const int row_base = bm + warp_m * 32 + (lane >> 2);
    const int col_base = bn + warp_n * 48 + (lane & 3) * 2;
#pragma unroll
    for (int mi = 0; mi < 2; mi++)
#pragma unroll
        for (int r2 = 0; r2 < 2; r2++) {
            int row = row_base + mi * 16 + r2 * 8;
#pragma unroll
            for (int ni = 0; ni < 6; ni++) {
                int col = col_base + ni * 8;
                if (col < N) {
                    float2 o;
                    o.x = acc[mi][ni][r2 * 2 + 0] + bias[col];
                    o.y = acc[mi][ni][r2 * 2 + 1] + bias[col + 1];
                    *reinterpret_cast<float2*>(&C[(size_t)row * N + col]) = o;
                }
            }
        }
}

// ================= q = query + query_pos ===================================
__global__ void add_kernel(const float* __restrict__ a, const float* __restrict__ b,
                           float* __restrict__ c, int n4) {
    int i = blockIdx.x * blockDim.x + threadIdx.x;
    if (i < n4) {
        float4 x = reinterpret_cast<const float4*>(a)[i];
        float4 y = reinterpret_cast<const float4*>(b)[i];
        float4 z;
        z.x = x.x + y.x; z.y = x.y + y.y; z.z = x.z + y.z; z.w = x.w + y.w;
        reinterpret_cast<float4*>(c)[i] = z;
    }
}

// ================= deformable 3D trilinear sampling ========================
__global__ __launch_bounds__(256)
void deform_sample(const float* __restrict__ v, const float* __restrict__ offs,
                   const float* __restrict__ lg, float* __restrict__ out) {
    int wg = (blockIdx.x * blockDim.x + threadIdx.x) >> 5;
    int lane = threadIdx.x & 31;
    const int total = BSZ * HEADS * NQ;
    if (wg >= total) return;

    int q    = wg % NQ;
    int head = (wg / NQ) % HEADS;
    int b    = wg / (NQ * HEADS);

    int qx = q % WW;
    int qy = q / WW;
    float refx = ((float)qx + 0.5f) / (float)WW;
    float refy = ((float)qy + 0.5f) / (float)HH;

    const float* lgp = lg + (((size_t)b * NQ + q) * HEADS + head) * NPTS;
    float wt[NPTS];
    float mx = -1e30f;
#pragma unroll
    for (int p = 0; p < NPTS; p++) mx = fmaxf(mx, lgp[p]);
    float s = 0.f;
#pragma unroll
    for (int p = 0; p < NPTS; p++) { wt[p] = expf(lgp[p] - mx); s += wt[p]; }
    float invs = 1.f / s;

    const float* offp = offs + ((((size_t)b * NQ + q) * HEADS + head) * NPTS) * 3;
    const float* vbh = v + (size_t)b * NV * EE + head * HD + lane;

    float acc = 0.f;
#pragma unroll
    for (int p = 0; p < NPTS; p++) {
        float ox = offp[p * 3 + 0];
        float oy = offp[p * 3 + 1];
        float oz = offp[p * 3 + 2];
        float x = (refx + ox / (float)WW) * (float)WW - 0.5f;
        float y = (refy + oy / (float)HH) * (float)HH - 0.5f;
        float z = (oz / (float)NFR) * (float)DDEP - 0.5f;
        float x0f = floorf(x), y0f = floorf(y), z0f = floorf(z);
        float fx = x - x0f, fy = y - y0f, fz = z - z0f;
        int ix0 = (int)x0f, iy0 = (int)y0f, iz0 = (int)z0f;
        float ap = wt[p] * invs;
#pragma unroll
        for (int dz = 0; dz < 2; dz++) {
            int zi = iz0 + dz;
            if ((unsigned)zi >= DDEP) continue;
            float wz = dz ? fz : (1.f - fz);
#pragma unroll
            for (int dy = 0; dy < 2; dy++) {
                int yi = iy0 + dy;
                if ((unsigned)yi >= HH) continue;
                float wzy = wz * (dy ? fy : (1.f - fy));
#pragma unroll
                for (int dx = 0; dx < 2; dx++) {
                    int xi = ix0 + dx;
                    if ((unsigned)xi >= WW) continue;
                    float wgt = wzy * (dx ? fx : (1.f - fx));
                    int idx = (zi * HH + yi) * WW + xi;
                    acc += ap * wgt * __ldg(&vbh[(size_t)idx * EE]);
                }
            }
        }
    }
    out[((size_t)b * NQ + q) * EE + head * HD + lane] = acc;
}

// ================= launch ==================================================
extern "C" void kernel_launch(void* const* d_in, const int* in_sizes, int n_in,
                              void* d_out, int out_size) {
    const float* query  = (const float*)d_in[0];
    const float* value  = (const float*)d_in[1];
    const float* qpos   = (const float*)d_in[2];
    const float* W_off  = (const float*)d_in[3];
    const float* b_off  = (const float*)d_in[4];
    const float* W_attn = (const float*)d_in[5];
    const float* b_attn = (const float*)d_in[6];
    const float* W_v    = (const float*)d_in[7];
    const float* b_v    = (const float*)d_in[8];
    const float* W_out  = (const float*)d_in[9];
    const float* b_out  = (const float*)d_in[10];
    float* out = (float*)d_out;

    float *q_s, *v_s, *offs_s, *attn_s, *samp_s;
    cudaGetSymbolAddress((void**)&q_s,    g_q);
    cudaGetSymbolAddress((void**)&v_s,    g_v);
    cudaGetSymbolAddress((void**)&offs_s, g_offs);
    cudaGetSymbolAddress((void**)&attn_s, g_attn);
    cudaGetSymbolAddress((void**)&samp_s, g_samp);

    static int smem_set = 0;
    if (!smem_set) {
        cudaFuncSetAttribute(gemm_mma, cudaFuncAttributeMaxDynamicSharedMemorySize, SMEM_TOT);
        smem_set = 1;
    }

    // 1) q = query + query_pos
    {
        int n4 = (BSZ * NQ * EE) / 4;
        add_kernel<<<(n4 + 255) / 256, 256>>>(query, qpos, q_s, n4);
    }
    // 2) v = value @ W_v + b_v   (M=51200, N=576)
    {
        dim3 grid(EE / BN, (BSZ * NV) / BM);
        gemm_mma<<<grid, 256, SMEM_TOT>>>(value, W_v, b_v, v_s, BSZ * NV, EE, EE);
    }
    // 3) offs = q @ W_off + b_off  (N=648)
    {
        int N = HEADS * NPTS * 3;
        dim3 grid((N + BN - 1) / BN, (BSZ * NQ) / BM);
        gemm_mma<<<grid, 256, SMEM_TOT>>>(q_s, W_off, b_off, offs_s, BSZ * NQ, N, EE);
    }
    // 4) attn logits = q @ W_attn + b_attn  (N=216)
    {
        int N = HEADS * NPTS;
        dim3 grid((N + BN - 1) / BN, (BSZ * NQ) / BM);
        gemm_mma<<<grid, 256, SMEM_TOT>>>(q_s, W_attn, b_attn, attn_s, BSZ * NQ, N, EE);
    }
    // 5) trilinear sampling + softmax weighting
    {
        int warps = BSZ * HEADS * NQ;
        int blocks = (warps + 7) / 8;
        deform_sample<<<blocks, 256>>>(v_s, offs_s, attn_s, samp_s);
    }
    // 6) out = samp @ W_out + b_out  (N=576)
    {
        dim3 grid(EE / BN, (BSZ * NQ) / BM);
        gemm_mma<<<grid, 256, SMEM_TOT>>>(samp_s, W_out, b_out, out, BSZ * NQ, EE, EE);
    }
}

// round 5
// speedup vs baseline: 1.9684x; 1.2381x over previous
#include <cuda_runtime.h>
#include <cuda_bf16.h>
#include <cstdint>
#include <math.h>

#define BSZ 2
#define HH 64
#define WW 80
#define NQ (HH*WW)          // 5120
#define EE 576
#define HEADS 18
#define HD 32
#define NPTS 12
#define NFR 3
#define DDEP 5
#define NV (NQ*DDEP)        // 25600
#define NOFF (HEADS*NPTS*3) // 648
#define NATT (HEADS*NPTS)   // 216

// ---------------- scratch (device globals; no allocation allowed) ----------
__device__ float g_v   [(size_t)BSZ*NV*EE];               // projected v (fp32)
__device__ float g_offs[(size_t)BSZ*NQ*NOFF];
__device__ float g_attn[(size_t)BSZ*NQ*NATT];

__device__ __align__(128) __nv_bfloat16 g_vh  [(size_t)BSZ*NV*EE];
__device__ __align__(128) __nv_bfloat16 g_vl  [(size_t)BSZ*NV*EE];
__device__ __align__(128) __nv_bfloat16 g_qh  [(size_t)BSZ*NQ*EE];
__device__ __align__(128) __nv_bfloat16 g_ql  [(size_t)BSZ*NQ*EE];
__device__ __align__(128) __nv_bfloat16 g_sph [(size_t)BSZ*NQ*EE];
__device__ __align__(128) __nv_bfloat16 g_spl [(size_t)BSZ*NQ*EE];
__device__ __align__(128) __nv_bfloat16 g_wvh [(size_t)EE*EE];
__device__ __align__(128) __nv_bfloat16 g_wvl [(size_t)EE*EE];
__device__ __align__(128) __nv_bfloat16 g_woh [(size_t)EE*NOFF];
__device__ __align__(128) __nv_bfloat16 g_wol [(size_t)EE*NOFF];
__device__ __align__(128) __nv_bfloat16 g_wah [(size_t)EE*NATT];
__device__ __align__(128) __nv_bfloat16 g_wal [(size_t)EE*NATT];
__device__ __align__(128) __nv_bfloat16 g_wuh [(size_t)EE*EE];
__device__ __align__(128) __nv_bfloat16 g_wul [(size_t)EE*EE];

// ================= helpers =================================================
__device__ __forceinline__ uint32_t smem_u32(const void* p) {
    uint32_t a;
    asm("{ .reg .u64 t; cvta.to.shared.u64 t, %1; cvt.u32.u64 %0, t; }" : "=r"(a) : "l"(p));
    return a;
}
__device__ __forceinline__ void ldsm_x4(uint32_t* r, uint32_t addr) {
    asm volatile("ldmatrix.sync.aligned.m8n8.x4.shared.b16 {%0,%1,%2,%3}, [%4];"
                 : "=r"(r[0]), "=r"(r[1]), "=r"(r[2]), "=r"(r[3]) : "r"(addr));
}
__device__ __forceinline__ void ldsm_x4_t(uint32_t* r, uint32_t addr) {
    asm volatile("ldmatrix.sync.aligned.m8n8.x4.trans.shared.b16 {%0,%1,%2,%3}, [%4];"
                 : "=r"(r[0]), "=r"(r[1]), "=r"(r[2]), "=r"(r[3]) : "r"(addr));
}
__device__ __forceinline__ void mma_bf16(float* c, const uint32_t* a, const uint32_t* b) {
    asm volatile(
        "mma.sync.aligned.m16n8k16.row.col.f32.bf16.bf16.f32 "
        "{%0,%1,%2,%3}, {%4,%5,%6,%7}, {%8,%9}, {%0,%1,%2,%3};"
        : "+f"(c[0]), "+f"(c[1]), "+f"(c[2]), "+f"(c[3])
        : "r"(a[0]), "r"(a[1]), "r"(a[2]), "r"(a[3]), "r"(b[0]), "r"(b[1]));
}
__device__ __forceinline__ void cp16(uint32_t dst, const void* src) {
    asm volatile("cp.async.ca.shared.global [%0], [%1], 16;" :: "r"(dst), "l"(src));
}
__device__ __forceinline__ void cp16p(uint32_t dst, const void* src, int srcsize) {
    asm volatile("cp.async.ca.shared.global [%0], [%1], 16, %2;" :: "r"(dst), "l"(src), "r"(srcsize));
}
#define CP_COMMIT() asm volatile("cp.async.commit_group;" ::: "memory")
#define CP_WAIT1()  asm volatile("cp.async.wait_group 1;" ::: "memory")

__device__ __forceinline__ void splitf(float f, unsigned short& h, unsigned short& l) {
    __nv_bfloat16 bh = __float2bfloat16(f);
    float r = f - __bfloat162float(bh);
    __nv_bfloat16 bl = __float2bfloat16(r);
    h = reinterpret_cast<unsigned short&>(bh);
    l = reinterpret_cast<unsigned short&>(bl);
}
__device__ __forceinline__ void split4(float4 v, uint2& hi, uint2& lo) {
    unsigned short h0, h1, h2, h3, l0, l1, l2, l3;
    splitf(v.x, h0, l0); splitf(v.y, h1, l1);
    splitf(v.z, h2, l2); splitf(v.w, h3, l3);
    hi.x = (uint32_t)h0 | ((uint32_t)h1 << 16);
    hi.y = (uint32_t)h2 | ((uint32_t)h3 << 16);
    lo.x = (uint32_t)l0 | ((uint32_t)l1 << 16);
    lo.y = (uint32_t)l2 | ((uint32_t)l3 << 16);
}

// ================= split / split-add =======================================
__global__ void split_kernel(const float4* __restrict__ in, uint2* __restrict__ hi,
                             uint2* __restrict__ lo, int n4) {
    int i = blockIdx.x * blockDim.x + threadIdx.x;
    if (i < n4) { uint2 h, l; split4(in[i], h, l); hi[i] = h; lo[i] = l; }
}
__global__ void split_add_kernel(const float4* __restrict__ a, const float4* __restrict__ b,
                                 uint2* __restrict__ hi, uint2* __restrict__ lo, int n4) {
    int i = blockIdx.x * blockDim.x + threadIdx.x;
    if (i < n4) {
        float4 x = a[i], y = b[i];
        float4 s = make_float4(x.x + y.x, x.y + y.y, x.z + y.z, x.w + y.w);
        uint2 h, l; split4(s, h, l); hi[i] = h; lo[i] = l;
    }
}

// ================= bf16 HMMA GEMM with cp.async pipeline ===================
// C[M,N] = (Ah+Al)(Bh+Bl) + bias, NPROD=3: AhBh+AhBl+AlBh ; NPROD=1: AhBh
// Block 128x96x32, 8 warps (4m x 2n), warp tile 32x48, 3 stages.
#define BM 128
#define BN 96
#define BK 32
#define STAGES 3
#define SA 80
#define SB 208
#define A_BYTES (128*SA)          // 10240
#define B_BYTES (32*SB)           // 6656
#define OFF_AH 0
#define OFF_AL A_BYTES
#define OFF_BH (2*A_BYTES)
#define OFF_BL (2*A_BYTES + B_BYTES)
#define STAGE_SZ (2*A_BYTES + 2*B_BYTES)   // 33792
#define SMEM_TOT (STAGES*STAGE_SZ)         // 101376

template<int NPROD>
__global__ __launch_bounds__(256, 2)
void gemm_bf16(const __nv_bfloat16* __restrict__ Ah, const __nv_bfloat16* __restrict__ Al,
               const __nv_bfloat16* __restrict__ Bh, const __nv_bfloat16* __restrict__ Bl,
               const float* __restrict__ bias, float* __restrict__ C,
               int M, int N, int K) {
    extern __shared__ char smem[];
    uint32_t sbase = smem_u32(smem);
    const int tid = threadIdx.x;
    const int lane = tid & 31, wid = tid >> 5;
    const int warp_m = wid & 3, warp_n = wid >> 2;
    const int bm = blockIdx.y * BM;
    const int bn = blockIdx.x * BN;
    const int nchunk = K / BK;

    // ---- tile loader (cp.async) ----
    auto load_chunk = [&](int c, int s) {
        const int k0 = c * BK;
        char* sb = smem + s * STAGE_SZ;
        // A: 128 rows x 64B = 512 x 16B
#pragma unroll
        for (int t = 0; t < 2; t++) {
            int idx = tid + t * 256, r = idx >> 2, c4 = idx & 3;
            uint32_t dst = smem_u32(sb + OFF_AH + r * SA + c4 * 16);
            cp16(dst, &Ah[(size_t)(bm + r) * K + k0 + c4 * 8]);
            if (NPROD == 3)
                cp16(dst + A_BYTES, &Al[(size_t)(bm + r) * K + k0 + c4 * 8]);
        }
        // B: 32 rows x 192B = 384 x 16B
#pragma unroll
        for (int t = 0; t < 2; t++) {
            int idx = tid + t * 256;
            if (idx < 384) {
                int r = idx / 12, g = idx % 12;
                int col = bn + g * 8;
                int sz = (col < N) ? 16 : 0;
                uint32_t dst = smem_u32(sb + OFF_BH + r * SB + g * 16);
                cp16p(dst, &Bh[(size_t)(k0 + r) * N + col], sz);
                if (NPROD == 3)
                    cp16p(dst + B_BYTES, &Bl[(size_t)(k0 + r) * N + col], sz);
            }
        }
    };

    float acc[2][6][4];
#pragma unroll
    for (int mi = 0; mi < 2; mi++)
#pragma unroll
        for (int ni = 0; ni < 6; ni++)
#pragma unroll
            for (int j = 0; j < 4; j++) acc[mi][ni][j] = 0.f;

    // prologue: stages 0,1
    load_chunk(0, 0); CP_COMMIT();
    load_chunk(1, 1); CP_COMMIT();

    for (int c = 0; c < nchunk; c++) {
        CP_WAIT1();
        __syncthreads();
        if (c + 2 < nchunk) load_chunk(c + 2, (c + 2) % STAGES);
        CP_COMMIT();

        uint32_t sbuf = sbase + (c % STAGES) * STAGE_SZ;
#pragma unroll
        for (int ks = 0; ks < 2; ks++) {
            uint32_t a_hi[2][4], a_lo[2][4], b_hi[6][2], b_lo[6][2];
#pragma unroll
            for (int mi = 0; mi < 2; mi++) {
                uint32_t ad = sbuf + OFF_AH
                    + (warp_m * 32 + mi * 16 + (lane & 15)) * SA
                    + ks * 32 + (lane >> 4) * 16;
                ldsm_x4(a_hi[mi], ad);
                if (NPROD == 3) ldsm_x4(a_lo[mi], ad + A_BYTES);
            }
#pragma unroll
            for (int nt = 0; nt < 3; nt++) {
                uint32_t bd = sbuf + OFF_BH
                    + (ks * 16 + (lane & 15)) * SB
                    + (warp_n * 48 + nt * 16) * 2 + (lane >> 4) * 16;
                uint32_t r[4];
                ldsm_x4_t(r, bd);
                b_hi[nt * 2][0] = r[0]; b_hi[nt * 2][1] = r[1];
                b_hi[nt * 2 + 1][0] = r[2]; b_hi[nt * 2 + 1][1] = r[3];
                if (NPROD == 3) {
                    ldsm_x4_t(r, bd + B_BYTES);
                    b_lo[nt * 2][0] = r[0]; b_lo[nt * 2][1] = r[1];
                    b_lo[nt * 2 + 1][0] = r[2]; b_lo[nt * 2 + 1][1] = r[3];
                }
            }
#pragma unroll
            for (int mi = 0; mi < 2; mi++)
#pragma unroll
                for (int ni = 0; ni < 6; ni++) {
                    mma_bf16(acc[mi][ni], a_hi[mi], b_hi[ni]);
                    if (NPROD == 3) {
                        mma_bf16(acc[mi][ni], a_hi[mi], b_lo[ni]);
                        mma_bf16(acc[mi][ni], a_lo[mi], b_hi[ni]);
                    }
                }
        }
        __syncthreads();
    }

    // ---- epilogue ----
    const int row_base = bm + warp_m * 32 + (lane >> 2);
    const int col_base = bn + warp_n * 48 + (lane & 3) * 2;
#pragma unroll
    for (int mi = 0; mi < 2; mi++)
#pragma unroll
        for (int r2 = 0; r2 < 2; r2++) {
            int row = row_base + mi * 16 + r2 * 8;
#pragma unroll
            for (int ni = 0; ni < 6; ni++) {
                int col = col_base + ni * 8;
                if (col < N) {
                    float2 o;
                    o.x = acc[mi][ni][r2 * 2 + 0] + bias[col];
                    o.y = acc[mi][ni][r2 * 2 + 1] + bias[col + 1];
                    *reinterpret_cast<float2*>(&C[(size_t)row * N + col]) = o;
                }
            }
        }
}

// ================= deformable 3D trilinear sampling ========================
__global__ __launch_bounds__(256)
void deform_sample(const float* __restrict__ v, const float* __restrict__ offs,
                   const float* __restrict__ lg,
                   __nv_bfloat16* __restrict__ oh, __nv_bfloat16* __restrict__ ol) {
    int wg = (blockIdx.x * blockDim.x + threadIdx.x) >> 5;
    int lane = threadIdx.x & 31;
    const int total = BSZ * HEADS * NQ;
    if (wg >= total) return;

    int q    = wg % NQ;
    int head = (wg / NQ) % HEADS;
    int b    = wg / (NQ * HEADS);

    int qx = q % WW;
    int qy = q / WW;
    float refx = ((float)qx + 0.5f) / (float)WW;
    float refy = ((float)qy + 0.5f) / (float)HH;

    const float* lgp = lg + (((size_t)b * NQ + q) * HEADS + head) * NPTS;
    float wt[NPTS];
    float mx = -1e30f;
#pragma unroll
    for (int p = 0; p < NPTS; p++) mx = fmaxf(mx, lgp[p]);
    float s = 0.f;
#pragma unroll
    for (int p = 0; p < NPTS; p++) { wt[p] = expf(lgp[p] - mx); s += wt[p]; }
    float invs = 1.f / s;

    const float* offp = offs + ((((size_t)b * NQ + q) * HEADS + head) * NPTS) * 3;
    const float* vbh = v + (size_t)b * NV * EE + head * HD + lane;

    float acc = 0.f;
#pragma unroll
    for (int p = 0; p < NPTS; p++) {
        float ox = offp[p * 3 + 0];
        float oy = offp[p * 3 + 1];
        float oz = offp[p * 3 + 2];
        float x = (refx + ox / (float)WW) * (float)WW - 0.5f;
        float y = (refy + oy / (float)HH) * (float)HH - 0.5f;
        float z = (oz / (float)NFR) * (float)DDEP - 0.5f;
        float x0f = floorf(x), y0f = floorf(y), z0f = floorf(z);
        float fx = x - x0f, fy = y - y0f, fz = z - z0f;
        int ix0 = (int)x0f, iy0 = (int)y0f, iz0 = (int)z0f;
        float ap = wt[p] * invs;
#pragma unroll
        for (int dz = 0; dz < 2; dz++) {
            int zi = iz0 + dz;
            if ((unsigned)zi >= DDEP) continue;
            float wz = dz ? fz : (1.f - fz);
#pragma unroll
            for (int dy = 0; dy < 2; dy++) {
                int yi = iy0 + dy;
                if ((unsigned)yi >= HH) continue;
                float wzy = wz * (dy ? fy : (1.f - fy));
#pragma unroll
                for (int dx = 0; dx < 2; dx++) {
                    int xi = ix0 + dx;
                    if ((unsigned)xi >= WW) continue;
                    float wgt = wzy * (dx ? fx : (1.f - fx));
                    int idx = (zi * HH + yi) * WW + xi;
                    acc += ap * wgt * __ldg(&vbh[(size_t)idx * EE]);
                }
            }
        }
    }
    unsigned short h, l;
    splitf(acc, h, l);
    size_t oidx = ((size_t)b * NQ + q) * EE + head * HD + lane;
    oh[oidx] = reinterpret_cast<__nv_bfloat16&>(h);
    ol[oidx] = reinterpret_cast<__nv_bfloat16&>(l);
}

// ================= launch ==================================================
extern "C" void kernel_launch(void* const* d_in, const int* in_sizes, int n_in,
                              void* d_out, int out_size) {
    const float* query  = (const float*)d_in[0];
    const float* value  = (const float*)d_in[1];
    const float* qpos   = (const float*)d_in[2];
    const float* W_off  = (const float*)d_in[3];
    const float* b_off  = (const float*)d_in[4];
    const float* W_attn = (const float*)d_in[5];
    const float* b_attn = (const float*)d_in[6];
    const float* W_v    = (const float*)d_in[7];
    const float* b_v    = (const float*)d_in[8];
    const float* W_out  = (const float*)d_in[9];
    const float* b_out  = (const float*)d_in[10];
    float* out = (float*)d_out;

    float *v_s, *offs_s, *attn_s;
    __nv_bfloat16 *vh, *vl, *qh, *ql, *sph, *spl;
    __nv_bfloat16 *wvh, *wvl, *woh, *wol, *wah, *wal, *wuh, *wul;
    cudaGetSymbolAddress((void**)&v_s,    g_v);
    cudaGetSymbolAddress((void**)&offs_s, g_offs);
    cudaGetSymbolAddress((void**)&attn_s, g_attn);
    cudaGetSymbolAddress((void**)&vh,  g_vh);  cudaGetSymbolAddress((void**)&vl,  g_vl);
    cudaGetSymbolAddress((void**)&qh,  g_qh);  cudaGetSymbolAddress((void**)&ql,  g_ql);
    cudaGetSymbolAddress((void**)&sph, g_sph); cudaGetSymbolAddress((void**)&spl, g_spl);
    cudaGetSymbolAddress((void**)&wvh, g_wvh); cudaGetSymbolAddress((void**)&wvl, g_wvl);
    cudaGetSymbolAddress((void**)&woh, g_woh); cudaGetSymbolAddress((void**)&wol, g_wol);
    cudaGetSymbolAddress((void**)&wah, g_wah); cudaGetSymbolAddress((void**)&wal, g_wal);
    cudaGetSymbolAddress((void**)&wuh, g_wuh); cudaGetSymbolAddress((void**)&wul, g_wul);

    static int smem_set = 0;
    if (!smem_set) {
        cudaFuncSetAttribute(gemm_bf16<3>, cudaFuncAttributeMaxDynamicSharedMemorySize, SMEM_TOT);
        cudaFuncSetAttribute(gemm_bf16<1>, cudaFuncAttributeMaxDynamicSharedMemorySize, SMEM_TOT);
        smem_set = 1;
    }

    // 1) splits
    {
        int n4 = (BSZ * NQ * EE) / 4;
        split_add_kernel<<<(n4 + 255) / 256, 256>>>(
            (const float4*)query, (const float4*)qpos, (uint2*)qh, (uint2*)ql, n4);
    }
    {
        int n4 = (BSZ * NV * EE) / 4;
        split_kernel<<<(n4 + 255) / 256, 256>>>((const float4*)value, (uint2*)vh, (uint2*)vl, n4);
    }
    {
        int n4 = (EE * EE) / 4;
        split_kernel<<<(n4 + 255) / 256, 256>>>((const float4*)W_v, (uint2*)wvh, (uint2*)wvl, n4);
        split_kernel<<<(n4 + 255) / 256, 256>>>((const float4*)W_out, (uint2*)wuh, (uint2*)wul, n4);
        int n4o = (EE * NOFF) / 4;
        split_kernel<<<(n4o + 255) / 256, 256>>>((const float4*)W_off, (uint2*)woh, (uint2*)wol, n4o);
        int n4a = (EE * NATT) / 4;
        split_kernel<<<(n4a + 255) / 256, 256>>>((const float4*)W_attn, (uint2*)wah, (uint2*)wal, n4a);
    }
    // 2) v = value @ W_v + b_v   (M=51200, N=576)
    {
        dim3 grid(EE / BN, (BSZ * NV) / BM);
        gemm_bf16<3><<<grid, 256, SMEM_TOT>>>(vh, vl, wvh, wvl, b_v, v_s, BSZ * NV, EE, EE);
    }
    // 3) offs = q @ W_off + b_off  (N=648)
    {
        dim3 grid((NOFF + BN - 1) / BN, (BSZ * NQ) / BM);
        gemm_bf16<1><<<grid, 256, SMEM_TOT>>>(qh, ql, woh, wol, b_off, offs_s, BSZ * NQ, NOFF, EE);
    }
    // 4) attn logits  (N=216)
    {
        dim3 grid((NATT + BN - 1) / BN, (BSZ * NQ) / BM);
        gemm_bf16<1><<<grid, 256, SMEM_TOT>>>(qh, ql, wah, wal, b_attn, attn_s, BSZ * NQ, NATT, EE);
    }
    // 5) trilinear sampling + softmax weighting -> bf16 hi/lo
    {
        int warps = BSZ * HEADS * NQ;
        int blocks = (warps + 7) / 8;
        deform_sample<<<blocks, 256>>>(v_s, offs_s, attn_s, sph, spl);
    }
    // 6) out = samp @ W_out + b_out  (N=576)
    {
        dim3 grid(EE / BN, (BSZ * NQ) / BM);
        gemm_bf16<3><<<grid, 256, SMEM_TOT>>>(sph, spl, wuh, wul, b_out, out, BSZ * NQ, EE, EE);
    }
}